// round 13
// baseline (speedup 1.0000x reference)
#include <cuda_runtime.h>

#define NN 1024
#define BB 128

// energy[b] = 0.5 * sum_{i<=j} W_ij * (1 + u_bi * u_bj),  u = 2v - 1.
// Grid (136, 4): 136 linearized upper-triangle 64x64 W tiles x 4 batch-groups of 32.
// Thread (bb 0..31, ig 0..7): 8 i-rows x 1 batch column, acc in registers.
// Mainloop FULLY unrolled -> all LDS addresses are base+immediate (no in-loop IMAD).
__global__ __launch_bounds__(256) void potts_kernel(const float* __restrict__ V,
                                                    const float* __restrict__ W,
                                                    float* __restrict__ out) {
    __shared__ float Ws[64][64];   // masked W tile [i][j]; float4 reads warp-uniform broadcast
    __shared__ float Uj[64][33];   // u tile (j-range); bank (j+b)%32 conflict-free both ways
    __shared__ float Ui[64][33];   // u tile (i-range), same layout

    // ---- Decode linear tile index -> (ti, tj) in upper triangle (16x16 tiles) ----
    int k = blockIdx.x;
    int ti = (int)((33.0f - sqrtf(1089.0f - 8.0f * (float)k)) * 0.5f);
    while (16 * (ti + 1) - ((ti + 1) * ti) / 2 <= k) ti++;
    while (16 * ti - (ti * (ti - 1)) / 2 > k) ti--;
    int tj = ti + (k - (16 * ti - (ti * (ti - 1)) / 2));

    int i0 = ti * 64, j0 = tj * 64, b0 = blockIdx.y * 32;
    int tid = threadIdx.x;
    bool diag = (ti == tj);

    // ---- Load W tile (coalesced float4), mask j<i on diagonal tiles ----
    {
        int r  = tid >> 4;          // 0..15
        int c4 = (tid & 15) << 2;   // 0,4,...,60
        #pragma unroll
        for (int rep = 0; rep < 4; rep++) {
            int row = r + rep * 16;
            float4 w = *(const float4*)&W[(size_t)(i0 + row) * NN + j0 + c4];
            if (diag) {
                if (c4 + 0 < row) w.x = 0.0f;
                if (c4 + 1 < row) w.y = 0.0f;
                if (c4 + 2 < row) w.z = 0.0f;
                if (c4 + 3 < row) w.w = 0.0f;
            }
            *(float4*)&Ws[row][c4] = w;
        }
    }
    // ---- Load u tiles: 64 j x 32 b each, coalesced gmem (lanes vary j) ----
    {
        int j  = tid & 63;
        int bq = tid >> 6;          // 0..3
        #pragma unroll
        for (int rep = 0; rep < 8; rep++) {
            int b = bq + rep * 4;   // 0..31
            float vj = V[(size_t)(b0 + b) * NN + j0 + j];
            Uj[j][b] = fmaf(2.0f, vj, -1.0f);
            float vi = V[(size_t)(b0 + b) * NN + i0 + j];
            Ui[j][b] = fmaf(2.0f, vi, -1.0f);
        }
    }
    __syncthreads();

    int bb = tid & 31;   // batch lane = lane id -> conflict-free u reads
    int ig = tid >> 5;   // i-group 0..7 (warp-uniform -> broadcast Ws reads)

    float acc[8];
    #pragma unroll
    for (int ii = 0; ii < 8; ii++) acc[ii] = 0.0f;

    // Fully unrolled: j4 is a compile-time constant -> LDS addrs = base + imm.
    #pragma unroll
    for (int j4 = 0; j4 < 64; j4 += 4) {
        float u0 = Uj[j4 + 0][bb];
        float u1 = Uj[j4 + 1][bb];
        float u2 = Uj[j4 + 2][bb];
        float u3 = Uj[j4 + 3][bb];
        #pragma unroll
        for (int ii = 0; ii < 8; ii++) {
            float4 w = *(const float4*)&Ws[ig * 8 + ii][j4];
            float a = acc[ii];
            a = fmaf(w.x, u0, a);
            a = fmaf(w.y, u1, a);
            a = fmaf(w.z, u2, a);
            a = fmaf(w.w, u3, a);
            acc[ii] = a;
        }
    }

    // ---- Tile row sums, parallel over all 256 threads:
    // thread (row = tid&63, ch = tid>>6) sums Ws[row][ch*16 .. +15] (rotated).
    __syncthreads();
    float* part = &Uj[0][0];           // Uj dead; floats [0..255] scratch, part[ch*64+row]
    {
        int row = tid & 63, ch = tid >> 6;
        float rs = 0.0f;
        #pragma unroll
        for (int q = 0; q < 16; q++) {
            int jj = ch * 16 + ((q + row) & 15);   // rotate: worst 2-way conflict
            rs += Ws[row][jj];
        }
        part[ch * 64 + row] = rs;      // bank = row%32 -> distinct per warp
    }
    __syncthreads();
    if (tid < 64) {                    // combine 4 chunk partials -> Ws[row][0]
        Ws[tid][0] = part[tid] + part[64 + tid] + part[128 + tid] + part[192 + tid];
    }
    __syncthreads();

    // ---- Per-thread: sum over its 8 rows of u_bi*Q_i(b) + its share of T0 ----
    float e = 0.0f;
    #pragma unroll
    for (int ii = 0; ii < 8; ii++) {
        e = fmaf(acc[ii], Ui[ig * 8 + ii][bb], e);   // row fixed -> base+imm
    }
    float t0 = 0.0f;
    #pragma unroll
    for (int ii = 0; ii < 8; ii++) t0 += Ws[ig * 8 + ii][0];   // broadcast reads

    // ---- Reduce 8 ig-groups per b in smem, then 1 atomic per b ----
    float* red = part + 256;           // Uj floats [256..511]: disjoint dead scratch
    red[ig * 32 + bb] = e + t0;        // bank = bb -> distinct
    __syncthreads();
    if (tid < 32) {
        float s = 0.0f;
        #pragma unroll
        for (int g = 0; g < 8; g++) s += red[g * 32 + tid];
        atomicAdd(&out[b0 + tid], 0.5f * s);
    }
}

extern "C" void kernel_launch(void* const* d_in, const int* in_sizes, int n_in,
                              void* d_out, int out_size) {
    // Defensive input identification by element count.
    const float* V = (const float*)d_in[0];
    const float* W = (const float*)d_in[1];
    if (n_in >= 2 && in_sizes[0] == NN * NN && in_sizes[1] == BB * NN) {
        V = (const float*)d_in[1];
        W = (const float*)d_in[0];
    }
    float* out = (float*)d_out;               // [128] fp32

    cudaMemsetAsync(out, 0, sizeof(float) * BB);   // out is poisoned; we accumulate into it
    dim3 grid(136, 4);                             // 136 upper-triangle tiles x 4 b-groups
    potts_kernel<<<grid, 256>>>(V, W, out);
}